// round 2
// baseline (speedup 1.0000x reference)
#include <cuda_runtime.h>
#include <math.h>

#define BATCH 4
#define SEQ   4096
#define DIM   1024

// ---- scratch (no cudaMalloc allowed) ----
__device__ float g_q[BATCH * SEQ * DIM];
__device__ float g_k[BATCH * SEQ * DIM];
__device__ float g_v[BATCH * SEQ * DIM];
__device__ float g_ctx[BATCH * SEQ * DIM];
__device__ float g_sc[(size_t)BATCH * SEQ * SEQ];   // 256 MB scores/probs

// ---------------------------------------------------------------------------
// Generic 128x128 tile SGEMM, BK=8, 256 threads, 8x8 accum per thread.
//   NT      : B is [N,K] row-major and we compute A @ B^T  (else B is [K,N])
//   CAUSAL  : skip blocks entirely above the diagonal (scores GEMM)
//   KLIMIT  : limit K loop to row_tile_end+1 (P@V causal GEMM)
//   HAS_BIAS: add bias[n]
//   SCALE   : multiply result by `scale`
// All dims must be multiples of tile sizes (true here: 16384/4096/1024, K%8==0).
// ---------------------------------------------------------------------------
template<bool NT, bool CAUSAL, bool KLIMIT, bool HAS_BIAS, bool SCALE>
__global__ __launch_bounds__(256)
void gemm128(const float* __restrict__ A, const float* __restrict__ Bm,
             const float* __restrict__ bias, float* __restrict__ C,
             int M, int N, int K, float scale,
             long sA, long sB, long sC)
{
    const int bz = blockIdx.z;
    A  += (long)bz * sA;
    Bm += (long)bz * sB;
    C  += (long)bz * sC;

    const int row0 = blockIdx.y * 128;
    const int col0 = blockIdx.x * 128;
    if (CAUSAL && col0 > row0) return;   // tile fully above diagonal

    int Keff = K;
    if (KLIMIT) {
        int lim = row0 + 128;
        Keff = lim < K ? lim : K;
    }

    __shared__ float As[8][128];
    __shared__ float Bs[8][128];

    const int t = threadIdx.x;

    // A-tile loader mapping (also reused for NT B-tile): one float4 per thread
    const int a_row = t >> 1;          // 0..127
    const int a_col = (t & 1) * 4;     // 0 or 4
    // B-tile loader mapping for NN
    const int b_row = t >> 5;          // 0..7
    const int b_col = (t & 31) * 4;    // 0..124

    const int ty = t >> 4;             // 0..15
    const int tx = t & 15;             // 0..15
    const int rbase = ty * 8;
    const int cbase = tx * 8;

    float acc[8][8];
    #pragma unroll
    for (int i = 0; i < 8; i++)
        #pragma unroll
        for (int j = 0; j < 8; j++) acc[i][j] = 0.f;

    const float* Aptr = A + (long)(row0 + a_row) * K + a_col;
    const float* Bptr = NT ? (Bm + (long)(col0 + a_row) * K + a_col)
                           : (Bm + (long)b_row * N + col0 + b_col);

    for (int k0 = 0; k0 < Keff; k0 += 8) {
        float4 av = *(const float4*)(Aptr + k0);
        As[a_col + 0][a_row] = av.x;
        As[a_col + 1][a_row] = av.y;
        As[a_col + 2][a_row] = av.z;
        As[a_col + 3][a_row] = av.w;
        if (NT) {
            float4 bv = *(const float4*)(Bptr + k0);
            Bs[a_col + 0][a_row] = bv.x;
            Bs[a_col + 1][a_row] = bv.y;
            Bs[a_col + 2][a_row] = bv.z;
            Bs[a_col + 3][a_row] = bv.w;
        } else {
            float4 bv = *(const float4*)(Bptr + (long)k0 * N);
            *(float4*)&Bs[b_row][b_col] = bv;
        }
        __syncthreads();

        #pragma unroll
        for (int kk = 0; kk < 8; kk++) {
            float ar[8], br[8];
            *(float4*)(ar)     = *(const float4*)&As[kk][rbase];
            *(float4*)(ar + 4) = *(const float4*)&As[kk][rbase + 4];
            *(float4*)(br)     = *(const float4*)&Bs[kk][cbase];
            *(float4*)(br + 4) = *(const float4*)&Bs[kk][cbase + 4];
            #pragma unroll
            for (int i = 0; i < 8; i++)
                #pragma unroll
                for (int j = 0; j < 8; j++)
                    acc[i][j] += ar[i] * br[j];
        }
        __syncthreads();
    }

    float bb[8];
    if (HAS_BIAS) {
        #pragma unroll
        for (int j = 0; j < 8; j++) bb[j] = bias[col0 + cbase + j];
    }

    #pragma unroll
    for (int i = 0; i < 8; i++) {
        float* cp = C + (long)(row0 + rbase + i) * N + col0 + cbase;
        float tmp[8];
        #pragma unroll
        for (int j = 0; j < 8; j++) {
            float v = acc[i][j];
            if (SCALE)    v *= scale;
            if (HAS_BIAS) v += bb[j];
            tmp[j] = v;
        }
        *(float4*)(cp)     = make_float4(tmp[0], tmp[1], tmp[2], tmp[3]);
        *(float4*)(cp + 4) = make_float4(tmp[4], tmp[5], tmp[6], tmp[7]);
    }
}

// ---------------------------------------------------------------------------
// Causal softmax over scores, in place.  One block per row.
// Row (b, i): valid entries j in [0, i]; zero-fill (i, roundup128(i+1)) so the
// causal P@V GEMM can run full 128-wide k-tiles.
// ---------------------------------------------------------------------------
__global__ __launch_bounds__(256)
void softmax_causal(float* __restrict__ sc)
{
    const long row = blockIdx.x;
    const int  b   = (int)(row >> 12);       // row / 4096
    const int  i   = (int)(row & 4095);
    float* p = sc + (long)b * SEQ * SEQ + (long)i * SEQ;
    const int L = i + 1;
    const int t = threadIdx.x;

    __shared__ float red[256];

    float m = -1e30f;
    for (int j = t; j < L; j += 256) m = fmaxf(m, p[j]);
    red[t] = m; __syncthreads();
    for (int s = 128; s > 0; s >>= 1) {
        if (t < s) red[t] = fmaxf(red[t], red[t + s]);
        __syncthreads();
    }
    m = red[0]; __syncthreads();

    float sum = 0.f;
    for (int j = t; j < L; j += 256) sum += __expf(p[j] - m);
    red[t] = sum; __syncthreads();
    for (int s = 128; s > 0; s >>= 1) {
        if (t < s) red[t] += red[t + s];
        __syncthreads();
    }
    const float inv = 1.0f / red[0];
    __syncthreads();

    const int Lpad = (L + 127) & ~127;
    for (int j = t; j < Lpad; j += 256)
        p[j] = (j < L) ? __expf(p[j] - m) * inv : 0.f;
}

// ---------------------------------------------------------------------------
extern "C" void kernel_launch(void* const* d_in, const int* in_sizes, int n_in,
                              void* d_out, int out_size)
{
    const float* x  = (const float*)d_in[0];
    const float* Wq = (const float*)d_in[1];
    const float* bq = (const float*)d_in[2];
    const float* Wk = (const float*)d_in[3];
    const float* bk = (const float*)d_in[4];
    const float* Wv = (const float*)d_in[5];
    const float* bv = (const float*)d_in[6];
    const float* Wo = (const float*)d_in[7];
    const float* bo = (const float*)d_in[8];
    float* out = (float*)d_out;

    float *q, *k, *v, *ctx, *sc;
    cudaGetSymbolAddress((void**)&q,   g_q);
    cudaGetSymbolAddress((void**)&k,   g_k);
    cudaGetSymbolAddress((void**)&v,   g_v);
    cudaGetSymbolAddress((void**)&ctx, g_ctx);
    cudaGetSymbolAddress((void**)&sc,  g_sc);

    const int M = BATCH * SEQ;                  // 16384
    const float scale = 1.0f / sqrtf((float)DIM);

    // 1) Q, K, V projections: [16384,1024] @ [1024,1024] + bias
    {
        dim3 grid(DIM / 128, M / 128, 1);
        gemm128<false, false, false, true, false><<<grid, 256>>>(
            x, Wq, bq, q, M, DIM, DIM, 1.f, 0, 0, 0);
        gemm128<false, false, false, true, false><<<grid, 256>>>(
            x, Wk, bk, k, M, DIM, DIM, 1.f, 0, 0, 0);
        gemm128<false, false, false, true, false><<<grid, 256>>>(
            x, Wv, bv, v, M, DIM, DIM, 1.f, 0, 0, 0);
    }

    // 2) scores = q @ k^T * scale  (per batch, lower-triangular tiles only)
    {
        dim3 grid(SEQ / 128, SEQ / 128, BATCH);
        gemm128<true, true, false, false, true><<<grid, 256>>>(
            q, k, nullptr, sc, SEQ, SEQ, DIM, scale,
            (long)SEQ * DIM, (long)SEQ * DIM, (long)SEQ * SEQ);
    }

    // 3) causal softmax in place
    softmax_causal<<<BATCH * SEQ, 256>>>(sc);

    // 4) ctx = P @ v  (per batch, k-loop limited to causal range)
    {
        dim3 grid(DIM / 128, SEQ / 128, BATCH);
        gemm128<false, false, true, false, false><<<grid, 256>>>(
            sc, v, nullptr, ctx, SEQ, DIM, SEQ, 1.f,
            (long)SEQ * SEQ, (long)SEQ * DIM, (long)SEQ * DIM);
    }

    // 5) out = ctx @ Wo + bo
    {
        dim3 grid(DIM / 128, M / 128, 1);
        gemm128<false, false, false, true, false><<<grid, 256>>>(
            ctx, Wo, bo, out, M, DIM, DIM, 1.f, 0, 0, 0);
    }
}

// round 6
// speedup vs baseline: 4.7074x; 4.7074x over previous
#include <cuda_runtime.h>
#include <cuda_fp16.h>
#include <stdint.h>

#define BATCH 4
#define SEQ   4096
#define DIM   1024
#define MTOT  (BATCH * SEQ)

// ---------------- scratch (no cudaMalloc allowed) ----------------
__device__ __half g_xh  [(long)MTOT * DIM];
__device__ __half g_qh  [(long)MTOT * DIM];
__device__ __half g_kh  [(long)MTOT * DIM];
__device__ float  g_v   [(long)MTOT * DIM];
__device__ __half g_vt  [(long)MTOT * DIM];        // [B][DIM][SEQ]
__device__ __half g_ctxh[(long)MTOT * DIM];
__device__ __half g_wqt [DIM * DIM];
__device__ __half g_wkt [DIM * DIM];
__device__ __half g_wvt [DIM * DIM];
__device__ __half g_wot [DIM * DIM];
__device__ float  g_sc  [(long)BATCH * SEQ * SEQ]; // fp32 scores
__device__ __half g_p   [(long)BATCH * SEQ * SEQ]; // fp16 probs (zero-padded)

// ---------------- PTX helpers (baseline ISA only: sm_80-era) ----------------
__device__ __forceinline__ uint32_t smem_u32(const void* p) {
    uint32_t a;
    asm("{ .reg .u64 t; cvta.to.shared.u64 t, %1; cvt.u32.u64 %0, t; }"
        : "=r"(a) : "l"(p));
    return a;
}
__device__ __forceinline__ void cp16(uint32_t s, const void* g) {
    asm volatile("cp.async.cg.shared.global [%0], [%1], 16;\n" :: "r"(s), "l"(g));
}
#define CP_COMMIT() asm volatile("cp.async.commit_group;\n" ::: "memory")
#define CP_WAIT0()  asm volatile("cp.async.wait_group 0;\n" ::: "memory")
#define CP_WAIT1()  asm volatile("cp.async.wait_group 1;\n" ::: "memory")

__device__ __forceinline__ void ldmx4(uint32_t* r, uint32_t addr) {
    asm volatile("ldmatrix.sync.aligned.m8n8.x4.shared.b16 {%0,%1,%2,%3}, [%4];"
                 : "=r"(r[0]), "=r"(r[1]), "=r"(r[2]), "=r"(r[3]) : "r"(addr));
}
__device__ __forceinline__ void mma16816(float* d, const uint32_t* a,
                                         uint32_t b0, uint32_t b1) {
    asm volatile("mma.sync.aligned.m16n8k16.row.col.f32.f16.f16.f32 "
                 "{%0,%1,%2,%3}, {%4,%5,%6,%7}, {%8,%9}, {%0,%1,%2,%3};"
                 : "+f"(d[0]), "+f"(d[1]), "+f"(d[2]), "+f"(d[3])
                 : "r"(a[0]), "r"(a[1]), "r"(a[2]), "r"(a[3]), "r"(b0), "r"(b1));
}

// ---------------- HMMA GEMM: C[M,N] = A[M,K] @ B[N,K]^T (fp16 in, f32 accum) -
// BM=128, BN=128, BK=32, 256 threads (8 warps, 2x4), warp tile 64x32.
static constexpr int BK   = 32;
static constexpr int SROW = 40;   // padded row stride in halves (80B)

template<int EPI /*0=f32,1=f16*/, bool BIAS, bool SCALE, bool CAUSAL, bool KLIMIT>
__global__ __launch_bounds__(256, 1)
void hmma_gemm(const __half* __restrict__ Ag, const __half* __restrict__ Bg,
               const float* __restrict__ bias,
               float* __restrict__ Cf, __half* __restrict__ Ch,
               int K, int ldA, int ldB, int ldC,
               long strA, long strB, long strC, float scale)
{
    __shared__ __half As[2][128 * SROW];
    __shared__ __half Bs[2][128 * SROW];

    const int bz = blockIdx.z;
    Ag += bz * strA;  Bg += bz * strB;
    const int row0 = blockIdx.y * 128;
    const int col0 = blockIdx.x * 128;
    if (CAUSAL && col0 > row0) return;          // tile fully above diagonal

    int Keff = K;
    if (KLIMIT) { int lim = row0 + 128; Keff = lim < K ? lim : K; }
    const int nst = Keff / BK;

    const int t      = threadIdx.x;
    const int lane   = t & 31;
    const int wid    = t >> 5;
    const int warp_m = wid >> 2;                // 0..1 -> m offset *64
    const int warp_n = wid & 3;                 // 0..3 -> n offset *32

    // ---- loader mapping: 512 16B-chunks per tile, 2 per thread ----
    // chunk c: row = c>>2 (0..127), cc = c&3 (16B sub-chunk within 64B row)
    auto load_stage = [&](int buf, int k0) {
        uint32_t sa = smem_u32(As[buf]);
        uint32_t sb = smem_u32(Bs[buf]);
#pragma unroll
        for (int i = 0; i < 2; i++) {
            int c = t + i * 256;
            int r = c >> 2, cc = c & 3;
            cp16(sa + r * (SROW * 2) + cc * 16,
                 (const char*)(Ag + (long)(row0 + r) * ldA + k0) + cc * 16);
        }
#pragma unroll
        for (int i = 0; i < 2; i++) {
            int c = t + i * 256;
            int r = c >> 2, cc = c & 3;
            cp16(sb + r * (SROW * 2) + cc * 16,
                 (const char*)(Bg + (long)(col0 + r) * ldB + k0) + cc * 16);
        }
    };

    float acc[4][4][4];
#pragma unroll
    for (int i = 0; i < 4; i++)
#pragma unroll
        for (int j = 0; j < 4; j++)
#pragma unroll
            for (int l = 0; l < 4; l++) acc[i][j][l] = 0.f;

    // ldmatrix per-lane address components
    const int la   = lane & 7;
    const int lb8  = (lane >> 3) & 1;
    const int lb16 = lane >> 4;
    // A x4: rows 0-7 klo | rows 8-15 klo | rows 0-7 khi | rows 8-15 khi
    const int aRow  = warp_m * 64 + la + 8 * lb8;    // + mt*16
    const int aColH = 8 * lb16;                      // + ks*16
    // B x4: n0-7 klo | n0-7 khi | n8-15 klo | n8-15 khi  -> 2 n-tiles per ld
    const int bRow  = warp_n * 32 + la + 8 * lb16;   // + ntp*16
    const int bColH = 8 * lb8;                       // + ks*16

    load_stage(0, 0); CP_COMMIT();

    for (int s = 0; s < nst; s++) {
        if (s + 1 < nst) { load_stage((s + 1) & 1, (s + 1) * BK); CP_COMMIT(); CP_WAIT1(); }
        else             { CP_WAIT0(); }
        __syncthreads();

        const uint32_t aB = smem_u32(As[s & 1]);
        const uint32_t bB = smem_u32(Bs[s & 1]);
#pragma unroll
        for (int ks = 0; ks < 2; ks++) {
            uint32_t ra[4][4], rb[2][4];
#pragma unroll
            for (int mt = 0; mt < 4; mt++)
                ldmx4(ra[mt], aB + (aRow + mt * 16) * (SROW * 2) + (aColH + ks * 16) * 2);
#pragma unroll
            for (int ntp = 0; ntp < 2; ntp++)
                ldmx4(rb[ntp], bB + (bRow + ntp * 16) * (SROW * 2) + (bColH + ks * 16) * 2);
#pragma unroll
            for (int mt = 0; mt < 4; mt++)
#pragma unroll
                for (int nt = 0; nt < 4; nt++)
                    mma16816(acc[mt][nt], ra[mt],
                             rb[nt >> 1][(nt & 1) * 2], rb[nt >> 1][(nt & 1) * 2 + 1]);
        }
        __syncthreads();   // all warps done reading this buffer before reuse
    }

    // ---- epilogue ----
#pragma unroll
    for (int mt = 0; mt < 4; mt++) {
#pragma unroll
        for (int nt = 0; nt < 4; nt++) {
            const int r  = row0 + warp_m * 64 + mt * 16 + (lane >> 2);
            const int c  = col0 + warp_n * 32 + nt * 8 + 2 * (lane & 3);
            float v0 = acc[mt][nt][0], v1 = acc[mt][nt][1];
            float v2 = acc[mt][nt][2], v3 = acc[mt][nt][3];
            if (BIAS) {
                float b0 = bias[c], b1 = bias[c + 1];
                v0 += b0; v1 += b1; v2 += b0; v3 += b1;
            }
            if (SCALE) { v0 *= scale; v1 *= scale; v2 *= scale; v3 *= scale; }
            if (EPI == 0) {
                float* p0 = Cf + bz * strC + (long)r * ldC + c;
                float* p1 = Cf + bz * strC + (long)(r + 8) * ldC + c;
                *(float2*)p0 = make_float2(v0, v1);
                *(float2*)p1 = make_float2(v2, v3);
            } else {
                __half* p0 = Ch + bz * strC + (long)r * ldC + c;
                __half* p1 = Ch + bz * strC + (long)(r + 8) * ldC + c;
                *(__half2*)p0 = __floats2half2_rn(v0, v1);
                *(__half2*)p1 = __floats2half2_rn(v2, v3);
            }
        }
    }
}

// ---------------- aux kernels ----------------
__global__ void cvt_f32_f16(const float* __restrict__ in, __half* __restrict__ out, long n) {
    long i = (long)blockIdx.x * blockDim.x + threadIdx.x;
    long stride = (long)gridDim.x * blockDim.x;
    for (; i < n; i += stride) out[i] = __float2half_rn(in[i]);
}

// out[c][r] = in[r][c], fp32 -> fp16.  in: [R,C], out: [C,R]
__global__ void transpose_cvt(const float* __restrict__ in, __half* __restrict__ out,
                              int R, int C, long inStride, long outStride) {
    __shared__ float tile[32][33];
    in  += (long)blockIdx.z * inStride;
    out += (long)blockIdx.z * outStride;
    int r0 = blockIdx.y * 32, c0 = blockIdx.x * 32;
    for (int i = threadIdx.y; i < 32; i += 8)
        tile[i][threadIdx.x] = in[(long)(r0 + i) * C + c0 + threadIdx.x];
    __syncthreads();
    for (int i = threadIdx.y; i < 32; i += 8)
        out[(long)(c0 + i) * R + r0 + threadIdx.x] = __float2half_rn(tile[threadIdx.x][i]);
}

// causal softmax: fp32 scores in, fp16 probs out, zero-padded to 128-boundary
__global__ __launch_bounds__(256)
void softmax_causal(const float* __restrict__ sc, __half* __restrict__ p) {
    const long row = blockIdx.x;
    const int  b = (int)(row >> 12);
    const int  i = (int)(row & 4095);
    const float* in = sc + (long)b * SEQ * SEQ + (long)i * SEQ;
    __half* out     = p  + (long)b * SEQ * SEQ + (long)i * SEQ;
    const int L = i + 1;
    const int t = threadIdx.x;
    __shared__ float red[256];

    float m = -1e30f;
    for (int j = t; j < L; j += 256) m = fmaxf(m, in[j]);
    red[t] = m; __syncthreads();
    for (int s = 128; s > 0; s >>= 1) {
        if (t < s) red[t] = fmaxf(red[t], red[t + s]);
        __syncthreads();
    }
    m = red[0]; __syncthreads();

    float sum = 0.f;
    for (int j = t; j < L; j += 256) sum += __expf(in[j] - m);
    red[t] = sum; __syncthreads();
    for (int s = 128; s > 0; s >>= 1) {
        if (t < s) red[t] += red[t + s];
        __syncthreads();
    }
    const float inv = 1.0f / red[0];
    __syncthreads();

    const int Lpad = (L + 127) & ~127;
    for (int j = t; j < Lpad; j += 256)
        out[j] = (j < L) ? __float2half_rn(__expf(in[j] - m) * inv) : __float2half_rn(0.f);
}

// ---------------------------------------------------------------------------
extern "C" void kernel_launch(void* const* d_in, const int* in_sizes, int n_in,
                              void* d_out, int out_size)
{
    const float* x  = (const float*)d_in[0];
    const float* Wq = (const float*)d_in[1];
    const float* bq = (const float*)d_in[2];
    const float* Wk = (const float*)d_in[3];
    const float* bk = (const float*)d_in[4];
    const float* Wv = (const float*)d_in[5];
    const float* bv = (const float*)d_in[6];
    const float* Wo = (const float*)d_in[7];
    const float* bo = (const float*)d_in[8];
    float* out = (float*)d_out;

    __half *xh, *qh, *kh, *vt, *ctxh, *wqt, *wkt, *wvt, *wot, *pp;
    float *v, *sc;
    cudaGetSymbolAddress((void**)&xh,   g_xh);
    cudaGetSymbolAddress((void**)&qh,   g_qh);
    cudaGetSymbolAddress((void**)&kh,   g_kh);
    cudaGetSymbolAddress((void**)&v,    g_v);
    cudaGetSymbolAddress((void**)&vt,   g_vt);
    cudaGetSymbolAddress((void**)&ctxh, g_ctxh);
    cudaGetSymbolAddress((void**)&wqt,  g_wqt);
    cudaGetSymbolAddress((void**)&wkt,  g_wkt);
    cudaGetSymbolAddress((void**)&wvt,  g_wvt);
    cudaGetSymbolAddress((void**)&wot,  g_wot);
    cudaGetSymbolAddress((void**)&sc,   g_sc);
    cudaGetSymbolAddress((void**)&pp,   g_p);

    const float scale = 1.0f / 32.0f;   // 1/sqrt(1024), exact

    // 0) fp32 -> fp16 conversions / weight transposes
    cvt_f32_f16<<<4096, 256>>>(x, xh, (long)MTOT * DIM);
    {
        dim3 blk(32, 8), grd(DIM / 32, DIM / 32, 1);
        transpose_cvt<<<grd, blk>>>(Wq, wqt, DIM, DIM, 0, 0);
        transpose_cvt<<<grd, blk>>>(Wk, wkt, DIM, DIM, 0, 0);
        transpose_cvt<<<grd, blk>>>(Wv, wvt, DIM, DIM, 0, 0);
        transpose_cvt<<<grd, blk>>>(Wo, wot, DIM, DIM, 0, 0);
    }

    // 1) projections: [16384,1024] @ Wt[1024,1024]^T
    {
        dim3 grid(DIM / 128, MTOT / 128, 1);
        hmma_gemm<1, true, true, false, false><<<grid, 256>>>(
            xh, wqt, bq, nullptr, qh, DIM, DIM, DIM, DIM, 0, 0, 0, scale);
        hmma_gemm<1, true, false, false, false><<<grid, 256>>>(
            xh, wkt, bk, nullptr, kh, DIM, DIM, DIM, DIM, 0, 0, 0, 1.f);
        hmma_gemm<0, true, false, false, false><<<grid, 256>>>(
            xh, wvt, bv, v, nullptr, DIM, DIM, DIM, DIM, 0, 0, 0, 1.f);
    }

    // 1b) v -> vT fp16  [B][DIM][SEQ]
    {
        dim3 blk(32, 8), grd(DIM / 32, SEQ / 32, BATCH);
        transpose_cvt<<<grd, blk>>>(v, vt, SEQ, DIM,
                                    (long)SEQ * DIM, (long)SEQ * DIM);
    }

    // 2) scores = q @ k^T (scale folded into q), causal tile skip, fp32 out
    {
        dim3 grid(SEQ / 128, SEQ / 128, BATCH);
        hmma_gemm<0, false, false, true, false><<<grid, 256>>>(
            qh, kh, nullptr, sc, nullptr, DIM, DIM, DIM, SEQ,
            (long)SEQ * DIM, (long)SEQ * DIM, (long)SEQ * SEQ, 1.f);
    }

    // 3) softmax -> fp16 probs, zero-padded to the KLIMIT boundary
    softmax_causal<<<BATCH * SEQ, 256>>>(sc, pp);

    // 4) ctx = P @ vT^T  (KLIMIT causal k-range), fp16 out
    {
        dim3 grid(DIM / 128, SEQ / 128, BATCH);
        hmma_gemm<1, false, false, false, true><<<grid, 256>>>(
            pp, vt, nullptr, nullptr, ctxh, SEQ, SEQ, SEQ, DIM,
            (long)SEQ * SEQ, (long)SEQ * DIM, (long)SEQ * DIM, 1.f);
    }

    // 5) out = ctx @ Wo^T + bo, fp32 out
    {
        dim3 grid(DIM / 128, MTOT / 128, 1);
        hmma_gemm<0, true, false, false, false><<<grid, 256>>>(
            ctxh, wot, bo, out, nullptr, DIM, DIM, DIM, DIM, 0, 0, 0, 1.f);
    }
}

// round 7
// speedup vs baseline: 6.1638x; 1.3094x over previous
#include <cuda_runtime.h>
#include <cuda_fp16.h>
#include <stdint.h>

#define BATCH 4
#define SEQ   4096
#define DIM   1024
#define MTOT  (BATCH * SEQ)
#define QKVN  (3 * DIM)

// ---------------- scratch (no cudaMalloc allowed) ----------------
__device__ __half g_xh   [(long)MTOT * DIM];
__device__ __half g_qkvh [(long)MTOT * QKVN];      // [B][SEQ][3*DIM]: q|k|v
__device__ __half g_vt   [(long)MTOT * DIM];       // [B][DIM][SEQ]
__device__ __half g_ctxh [(long)MTOT * DIM];
__device__ __half g_wqkvt[(long)QKVN * DIM];       // [3*DIM][DIM] rows=out-col
__device__ __half g_wot  [DIM * DIM];
__device__ float  g_bqkv [QKVN];
__device__ float  g_sc   [(long)BATCH * SEQ * SEQ]; // fp32 scores
__device__ __half g_p    [(long)BATCH * SEQ * SEQ]; // fp16 probs (zero-padded)

// ---------------- PTX helpers (baseline ISA only) ----------------
__device__ __forceinline__ uint32_t smem_u32(const void* p) {
    uint32_t a;
    asm("{ .reg .u64 t; cvta.to.shared.u64 t, %1; cvt.u32.u64 %0, t; }"
        : "=r"(a) : "l"(p));
    return a;
}
__device__ __forceinline__ void cp16(uint32_t s, const void* g) {
    asm volatile("cp.async.cg.shared.global [%0], [%1], 16;\n" :: "r"(s), "l"(g));
}
#define CP_COMMIT() asm volatile("cp.async.commit_group;\n" ::: "memory")
#define CP_WAIT1()  asm volatile("cp.async.wait_group 1;\n" ::: "memory")

__device__ __forceinline__ void ldmx4(uint32_t* r, uint32_t addr) {
    asm volatile("ldmatrix.sync.aligned.m8n8.x4.shared.b16 {%0,%1,%2,%3}, [%4];"
                 : "=r"(r[0]), "=r"(r[1]), "=r"(r[2]), "=r"(r[3]) : "r"(addr));
}
__device__ __forceinline__ void mma16816(float* d, const uint32_t* a,
                                         uint32_t b0, uint32_t b1) {
    asm volatile("mma.sync.aligned.m16n8k16.row.col.f32.f16.f16.f32 "
                 "{%0,%1,%2,%3}, {%4,%5,%6,%7}, {%8,%9}, {%0,%1,%2,%3};"
                 : "+f"(d[0]), "+f"(d[1]), "+f"(d[2]), "+f"(d[3])
                 : "r"(a[0]), "r"(a[1]), "r"(a[2]), "r"(a[3]), "r"(b0), "r"(b1));
}

// ---------------- HMMA GEMM: C[M,N] = A[M,K] @ B[N,K]^T -------------------
// BM=128, BN=128, BK=64, 3-stage cp.async pipeline, one sync per stage.
// 256 threads (8 warps 2x4), warp tile 64x32, fragments register-double-buffered.
static constexpr int BK      = 64;
static constexpr int SROW    = 72;                 // padded row stride (halves)
static constexpr int SROWB   = SROW * 2;           // 144 bytes
static constexpr int TILE_B  = 128 * SROWB;        // 18432
static constexpr int STAGE_B = 2 * TILE_B;         // 36864
static constexpr int SMEM_DYN = 3 * STAGE_B;       // 110592

template<int EPI /*0=f32,1=f16*/, bool BIAS, bool CAUSAL, bool KLIMIT>
__global__ __launch_bounds__(256, 1)
void hmma_gemm(const __half* __restrict__ Ag, const __half* __restrict__ Bg,
               const float* __restrict__ bias,
               float* __restrict__ Cf, __half* __restrict__ Ch,
               int K, int ldA, int ldB, int ldC,
               long strA, long strB, long strC)
{
    extern __shared__ __align__(16) char dsm[];

    const int bz = blockIdx.z;
    Ag += bz * strA;  Bg += bz * strB;
    const int row0 = blockIdx.y * 128;
    const int col0 = blockIdx.x * 128;
    if (CAUSAL && col0 > row0) return;             // tile fully above diagonal

    int Keff = K;
    if (KLIMIT) { int lim = row0 + 128; Keff = lim < K ? lim : K; }
    const int nst = Keff / BK;                     // >= 2 always here

    const int t      = threadIdx.x;
    const int lane   = t & 31;
    const int wid    = t >> 5;
    const int warp_m = wid >> 2;                   // 0..1 -> m*64
    const int warp_n = wid & 3;                    // 0..3 -> n*32

    const uint32_t sbase = smem_u32(dsm);

    // loader: 1024 16B-chunks per 128x64 tile; 4 A + 4 B chunks per thread
    auto load_stage = [&](int buf, int k0) {
        uint32_t sa = sbase + buf * STAGE_B;
        uint32_t sb = sa + TILE_B;
#pragma unroll
        for (int i = 0; i < 4; i++) {
            int c = t + i * 256;
            int r = c >> 3, cc = c & 7;
            cp16(sa + r * SROWB + cc * 16,
                 (const char*)(Ag + (long)(row0 + r) * ldA + k0) + cc * 16);
        }
#pragma unroll
        for (int i = 0; i < 4; i++) {
            int c = t + i * 256;
            int r = c >> 3, cc = c & 7;
            cp16(sb + r * SROWB + cc * 16,
                 (const char*)(Bg + (long)(col0 + r) * ldB + k0) + cc * 16);
        }
    };

    // ldmatrix per-lane address components
    const int la   = lane & 7;
    const int lb8  = (lane >> 3) & 1;
    const int lb16 = lane >> 4;
    const int aRow  = warp_m * 64 + la + 8 * lb8;   // + mt*16
    const int aColH = 8 * lb16;                     // + ks*16 (halves)
    const int bRow  = warp_n * 32 + la + 8 * lb16;  // + ntp*16
    const int bColH = 8 * lb8;                      // + ks*16 (halves)

    auto ld_frags = [&](uint32_t aB, uint32_t bB, int ks,
                        uint32_t ra[4][4], uint32_t rb[2][4]) {
#pragma unroll
        for (int mt = 0; mt < 4; mt++)
            ldmx4(ra[mt], aB + (uint32_t)(aRow + mt * 16) * SROWB + (aColH + ks * 16) * 2);
#pragma unroll
        for (int ntp = 0; ntp < 2; ntp++)
            ldmx4(rb[ntp], bB + (uint32_t)(bRow + ntp * 16) * SROWB + (bColH + ks * 16) * 2);
    };

    float acc[4][4][4];
#pragma unroll
    for (int i = 0; i < 4; i++)
#pragma unroll
        for (int j = 0; j < 4; j++)
#pragma unroll
            for (int l = 0; l < 4; l++) acc[i][j][l] = 0.f;

    load_stage(0, 0);   CP_COMMIT();
    load_stage(1, BK);  CP_COMMIT();
    CP_WAIT1();                                    // stage 0 resident
    __syncthreads();

    uint32_t ra[2][4][4], rb[2][2][4];
    int buf = 0;
    for (int s = 0; s < nst; s++) {
        const uint32_t aB = sbase + buf * STAGE_B;
        const uint32_t bB = aB + TILE_B;

        ld_frags(aB, bB, 0, ra[0], rb[0]);

        // issue loads for stage s+2 (buffer (buf+2)%3, safe: all warps synced
        // past compute of stage s-1 which last read that buffer)
        const int tno = s + 2;
        if (tno < nst) load_stage((buf + 2) % 3, tno * BK);
        CP_COMMIT();                               // uniform group count

#pragma unroll
        for (int ks = 0; ks < 4; ks++) {
            const int cb = ks & 1, nb = cb ^ 1;
            if (ks < 3) ld_frags(aB, bB, ks + 1, ra[nb], rb[nb]);
#pragma unroll
            for (int mt = 0; mt < 4; mt++)
#pragma unroll
                for (int nt = 0; nt < 4; nt++)
                    mma16816(acc[mt][nt], ra[cb][mt],
                             rb[cb][nt >> 1][(nt & 1) * 2],
                             rb[cb][nt >> 1][(nt & 1) * 2 + 1]);
        }

        CP_WAIT1();                                // stage s+1 resident
        __syncthreads();
        buf = (buf + 1) % 3;
    }

    // ---- epilogue ----
#pragma unroll
    for (int mt = 0; mt < 4; mt++) {
#pragma unroll
        for (int nt = 0; nt < 4; nt++) {
            const int r = row0 + warp_m * 64 + mt * 16 + (lane >> 2);
            const int c = col0 + warp_n * 32 + nt * 8 + 2 * (lane & 3);
            float v0 = acc[mt][nt][0], v1 = acc[mt][nt][1];
            float v2 = acc[mt][nt][2], v3 = acc[mt][nt][3];
            if (BIAS) {
                float b0 = bias[c], b1 = bias[c + 1];
                v0 += b0; v1 += b1; v2 += b0; v3 += b1;
            }
            if (EPI == 0) {
                float* p0 = Cf + bz * strC + (long)r * ldC + c;
                float* p1 = Cf + bz * strC + (long)(r + 8) * ldC + c;
                *(float2*)p0 = make_float2(v0, v1);
                *(float2*)p1 = make_float2(v2, v3);
            } else {
                __half* p0 = Ch + bz * strC + (long)r * ldC + c;
                __half* p1 = Ch + bz * strC + (long)(r + 8) * ldC + c;
                *(__half2*)p0 = __floats2half2_rn(v0, v1);
                *(__half2*)p1 = __floats2half2_rn(v2, v3);
            }
        }
    }
}

// ---------------- aux kernels ----------------
__global__ void cvt_f32_f16_v(const float4* __restrict__ in, __half2* __restrict__ out, long n4) {
    long i = (long)blockIdx.x * blockDim.x + threadIdx.x;
    long stride = (long)gridDim.x * blockDim.x;
    for (; i < n4; i += stride) {
        float4 v = in[i];
        out[2 * i]     = __floats2half2_rn(v.x, v.y);
        out[2 * i + 1] = __floats2half2_rn(v.z, v.w);
    }
}

__global__ void bias_concat(const float* __restrict__ bq, const float* __restrict__ bk,
                            const float* __restrict__ bv, float* __restrict__ o, float s) {
    int i = blockIdx.x * blockDim.x + threadIdx.x;
    if (i >= QKVN) return;
    if (i < DIM)            o[i] = bq[i] * s;
    else if (i < 2 * DIM)   o[i] = bk[i - DIM];
    else                    o[i] = bv[i - 2 * DIM];
}

// out[n][k] = in[k][n] * s   (fp32 [1024,1024] -> fp16 section)
__global__ void transpose_cvt_s(const float* __restrict__ in, __half* __restrict__ out, float s) {
    __shared__ float tile[32][33];
    int r0 = blockIdx.y * 32, c0 = blockIdx.x * 32;
    for (int i = threadIdx.y; i < 32; i += 8)
        tile[i][threadIdx.x] = in[(long)(r0 + i) * DIM + c0 + threadIdx.x];
    __syncthreads();
    for (int i = threadIdx.y; i < 32; i += 8)
        out[(long)(c0 + i) * DIM + r0 + threadIdx.x] =
            __float2half_rn(tile[threadIdx.x][i] * s);
}

// fp16 transpose: out[(c0+i)][r0+tx] = in[(r0+i)][c0+tx]
__global__ void transpose_h(const __half* __restrict__ in, __half* __restrict__ out,
                            int ldin, int ldout, long inStride, long outStride) {
    __shared__ __half tile[32][34];
    in  += (long)blockIdx.z * inStride;
    out += (long)blockIdx.z * outStride;
    int r0 = blockIdx.y * 32, c0 = blockIdx.x * 32;
    for (int i = threadIdx.y; i < 32; i += 8)
        tile[i][threadIdx.x] = in[(long)(r0 + i) * ldin + c0 + threadIdx.x];
    __syncthreads();
    for (int i = threadIdx.y; i < 32; i += 8)
        out[(long)(c0 + i) * ldout + r0 + threadIdx.x] = tile[threadIdx.x][i];
}

// causal softmax: fp32 scores in, fp16 probs out, zero-padded to 128-boundary
__global__ __launch_bounds__(256)
void softmax_causal(const float* __restrict__ sc, __half* __restrict__ p) {
    const long row = blockIdx.x;
    const int  b = (int)(row >> 12);
    const int  i = (int)(row & 4095);
    const float* in = sc + (long)b * SEQ * SEQ + (long)i * SEQ;
    __half* out     = p  + (long)b * SEQ * SEQ + (long)i * SEQ;
    const int L = i + 1;
    const int t = threadIdx.x;
    __shared__ float red[256];

    float m = -1e30f;
    for (int j = t; j < L; j += 256) m = fmaxf(m, in[j]);
    red[t] = m; __syncthreads();
    for (int s = 128; s > 0; s >>= 1) {
        if (t < s) red[t] = fmaxf(red[t], red[t + s]);
        __syncthreads();
    }
    m = red[0]; __syncthreads();

    float sum = 0.f;
    for (int j = t; j < L; j += 256) sum += __expf(in[j] - m);
    red[t] = sum; __syncthreads();
    for (int s = 128; s > 0; s >>= 1) {
        if (t < s) red[t] += red[t + s];
        __syncthreads();
    }
    const float inv = 1.0f / red[0];
    __syncthreads();

    const int Lpad = (L + 127) & ~127;
    for (int j = t; j < Lpad; j += 256)
        out[j] = (j < L) ? __float2half_rn(__expf(in[j] - m) * inv) : __float2half_rn(0.f);
}

// ---------------------------------------------------------------------------
extern "C" void kernel_launch(void* const* d_in, const int* in_sizes, int n_in,
                              void* d_out, int out_size)
{
    const float* x  = (const float*)d_in[0];
    const float* Wq = (const float*)d_in[1];
    const float* bq = (const float*)d_in[2];
    const float* Wk = (const float*)d_in[3];
    const float* bk = (const float*)d_in[4];
    const float* Wv = (const float*)d_in[5];
    const float* bv = (const float*)d_in[6];
    const float* Wo = (const float*)d_in[7];
    const float* bo = (const float*)d_in[8];
    float* out = (float*)d_out;

    __half *xh, *qkvh, *vt, *ctxh, *wqkvt, *wot, *pp;
    float *sc, *bqkv;
    cudaGetSymbolAddress((void**)&xh,    g_xh);
    cudaGetSymbolAddress((void**)&qkvh,  g_qkvh);
    cudaGetSymbolAddress((void**)&vt,    g_vt);
    cudaGetSymbolAddress((void**)&ctxh,  g_ctxh);
    cudaGetSymbolAddress((void**)&wqkvt, g_wqkvt);
    cudaGetSymbolAddress((void**)&wot,   g_wot);
    cudaGetSymbolAddress((void**)&sc,    g_sc);
    cudaGetSymbolAddress((void**)&pp,    g_p);
    cudaGetSymbolAddress((void**)&bqkv,  g_bqkv);

    cudaFuncSetAttribute(hmma_gemm<1, true,  false, false>, cudaFuncAttributeMaxDynamicSharedMemorySize, SMEM_DYN);
    cudaFuncSetAttribute(hmma_gemm<0, false, true,  false>, cudaFuncAttributeMaxDynamicSharedMemorySize, SMEM_DYN);
    cudaFuncSetAttribute(hmma_gemm<1, false, false, true >, cudaFuncAttributeMaxDynamicSharedMemorySize, SMEM_DYN);
    cudaFuncSetAttribute(hmma_gemm<0, true,  false, false>, cudaFuncAttributeMaxDynamicSharedMemorySize, SMEM_DYN);

    const float scale = 1.0f / 32.0f;   // 1/sqrt(1024), exact power of two

    // 0) conversions: x -> fp16; weights -> transposed fp16 (scale folded into Wq)
    cvt_f32_f16_v<<<2048, 256>>>((const float4*)x, (__half2*)xh, (long)MTOT * DIM / 4);
    bias_concat<<<(QKVN + 255) / 256, 256>>>(bq, bk, bv, bqkv, scale);
    {
        dim3 blk(32, 8), grd(DIM / 32, DIM / 32);
        transpose_cvt_s<<<grd, blk>>>(Wq, wqkvt,                 scale);
        transpose_cvt_s<<<grd, blk>>>(Wk, wqkvt + (long)DIM*DIM, 1.f);
        transpose_cvt_s<<<grd, blk>>>(Wv, wqkvt + (long)2*DIM*DIM, 1.f);
        transpose_cvt_s<<<grd, blk>>>(Wo, wot,                   1.f);
    }

    // 1) fused QKV projection: qkvh[M,3072] = xh @ Wqkv^T + bqkv
    {
        dim3 grid(QKVN / 128, MTOT / 128, 1);
        hmma_gemm<1, true, false, false><<<grid, 256, SMEM_DYN>>>(
            xh, wqkvt, bqkv, nullptr, qkvh, DIM, DIM, DIM, QKVN, 0, 0, 0);
    }

    // 1b) v section -> vT fp16 [B][DIM][SEQ]
    {
        dim3 blk(32, 8), grd(DIM / 32, SEQ / 32, BATCH);
        transpose_h<<<grd, blk>>>(qkvh + 2 * DIM, vt, QKVN, SEQ,
                                  (long)SEQ * QKVN, (long)DIM * SEQ);
    }

    // 2) scores = q @ k^T (scale folded into q), causal tile skip, fp32 out
    {
        dim3 grid(SEQ / 128, SEQ / 128, BATCH);
        hmma_gemm<0, false, true, false><<<grid, 256, SMEM_DYN>>>(
            qkvh, qkvh + DIM, nullptr, sc, nullptr, DIM, QKVN, QKVN, SEQ,
            (long)SEQ * QKVN, (long)SEQ * QKVN, (long)SEQ * SEQ);
    }

    // 3) softmax -> fp16 probs, zero-padded
    softmax_causal<<<BATCH * SEQ, 256>>>(sc, pp);

    // 4) ctx = P @ vT^T  (KLIMIT causal k-range), fp16 out
    {
        dim3 grid(DIM / 128, SEQ / 128, BATCH);
        hmma_gemm<1, false, false, true><<<grid, 256, SMEM_DYN>>>(
            pp, vt, nullptr, nullptr, ctxh, SEQ, SEQ, SEQ, DIM,
            (long)SEQ * SEQ, (long)SEQ * DIM, (long)SEQ * DIM);
    }

    // 5) out = ctx @ Wo^T + bo, fp32 out
    {
        dim3 grid(DIM / 128, MTOT / 128, 1);
        hmma_gemm<0, true, false, false><<<grid, 256, SMEM_DYN>>>(
            ctxh, wot, bo, out, nullptr, DIM, DIM, DIM, DIM, 0, 0, 0);
    }
}